// round 4
// baseline (speedup 1.0000x reference)
#include <cuda_runtime.h>
#include <cuda_bf16.h>

// LocalCrossLinearTrf: B=2, D=H=W=64, F_IN=F_OUT=8.
// out[b,z,y,w,j] = sum_i trilinear(x[b,:,:,:,i], (z,y,w)+trf[z,y,w,i,j,:]) * mult[z,y,w,i,j]
//                  + 8*bias[z,y,w,j]
//
// R3: thread = (w, i) [was (w, j)].
//  - trf reads become 6x LDG.128 of contiguous memory per thread (no sector waste)
//  - mult becomes 2x LDG.128
//  - smem x-neighborhood layout gets i-stride 65 f2 (odd) + slab stride 523 f2
//    so same-w warp octets (distinct i) hit distinct bank-pairs
//  - per-j sum over i done with a 3-stage shfl.xor butterfly; lane i keeps j=i
// Both batches ride together in each 8B smem slot, lerped with packed f32x2.

typedef unsigned long long ull;

__device__ __forceinline__ ull pack2(float a, float b) {
    ull r; asm("mov.b64 %0, {%1,%2};" : "=l"(r) : "f"(a), "f"(b)); return r;
}
__device__ __forceinline__ void unpack2(ull v, float& a, float& b) {
    asm("mov.b64 {%0,%1}, %2;" : "=f"(a), "=f"(b) : "l"(v));
}
__device__ __forceinline__ ull fma2(ull a, ull b, ull c) {
    ull d; asm("fma.rn.f32x2 %0, %1, %2, %3;" : "=l"(d) : "l"(a), "l"(b), "l"(c)); return d;
}
__device__ __forceinline__ ull mul2(ull a, ull b) {
    ull d; asm("mul.rn.f32x2 %0, %1, %2;" : "=l"(d) : "l"(a), "l"(b)); return d;
}
__device__ __forceinline__ ull add2(ull a, ull b) {
    ull d; asm("add.rn.f32x2 %0, %1, %2;" : "=l"(d) : "l"(a), "l"(b)); return d;
}

// smem layout in float2 (=8B both-batch) units:
//   f2_index = slab*SLAB_F2 + i*I_F2 + x,   slab = sz*3+sy in 0..8, x in 0..63
// I_F2 = 65 (odd: per-i bank-pair shift of 1), SLAB_F2 = 8*65+3 = 523 (== 11 mod 16).
#define I_F2     65
#define SLAB_F2  523
#define SMEM_F   (9 * SLAB_F2 * 2)   // 9414 floats = 37656 B

__global__ __launch_bounds__(512, 2)
void lclt_kernel(const float* __restrict__ x,     // [2,64,64,64,8]
                 const float* __restrict__ mult,  // [64,64,64,8,8]
                 const float* __restrict__ trf,   // [64,64,64,8,8,3]
                 const float* __restrict__ bias,  // [64,64,64,8]
                 float* __restrict__ out)         // [2,64,64,64,8]
{
    __shared__ float sm[SMEM_F];

    const int tid = threadIdx.x;
    const int y = blockIdx.x, z = blockIdx.y;

    // ---- Stage x 3x3 (z,y)-neighborhood, both batches, all 8 channels.
    // 18 (szy,b) slabs * 128 float4 reads = 2304 vectors over 512 threads.
    for (int k = tid; k < 18 * 128; k += 512) {
        int slab = k >> 7;             // = szy*2 + b
        int q    = k & 127;
        int b    = slab & 1;
        int szy  = slab >> 1;
        int sz   = szy / 3, sy = szy - sz * 3;
        int zz = min(max(z - 1 + sz, 0), 63);
        int yy = min(max(y - 1 + sy, 0), 63);
        int w  = q >> 1;
        int ip = (q & 1) << 2;         // channel group 0 or 4
        float4 v = *reinterpret_cast<const float4*>(
            x + (((b * 64 + zz) * 64 + yy) * 64 + w) * 8 + ip);
        float* dst = sm + szy * (SLAB_F2 * 2) + w * 2 + b;
        dst[(ip + 0) * (I_F2 * 2)] = v.x;
        dst[(ip + 1) * (I_F2 * 2)] = v.y;
        dst[(ip + 2) * (I_F2 * 2)] = v.z;
        dst[(ip + 3) * (I_F2 * 2)] = v.w;
    }
    __syncthreads();

    const int w = tid >> 3;        // 0..63
    const int i = tid & 7;         // input channel owned by this lane
    const int vox = (z * 64 + y) * 64 + w;
    const float zf = (float)z, yf = (float)y, wf = (float)w;

    // trf for (w,i): 24 contiguous floats (j-major, xyz inner), 16B aligned.
    const float4* trfp4 = reinterpret_cast<const float4*>(trf + vox * 192 + i * 24);
    // mult for (w,i): 8 contiguous floats.
    const float4* mp4 = reinterpret_cast<const float4*>(mult + vox * 64 + i * 8);
    float4 m0 = mp4[0], m1 = mp4[1];
    const float mj[8] = { m0.x, m0.y, m0.z, m0.w, m1.x, m1.y, m1.z, m1.w };

    const ull* S2 = reinterpret_cast<const ull*>(sm);
    const int ibase = i * I_F2;

    ull res = 0ull;  // this lane's final (j == i) packed pair

    union { float4 v4[3]; float f[12]; } T;

    #pragma unroll
    for (int half = 0; half < 2; half++) {
        T.v4[0] = trfp4[half * 3 + 0];
        T.v4[1] = trfp4[half * 3 + 1];
        T.v4[2] = trfp4[half * 3 + 2];

        #pragma unroll
        for (int jj = 0; jj < 4; jj++) {
            const int j = half * 4 + jj;
            float tz = T.f[jj * 3 + 0];
            float ty = T.f[jj * 3 + 1];
            float tx = T.f[jj * 3 + 2];

            float locz = zf + tz, locy = yf + ty, locx = wf + tx;

            float clz = fminf(fmaxf(locz, 0.f), 63.f);
            float cly = fminf(fmaxf(locy, 0.f), 63.f);
            float clx = fminf(fmaxf(locx, 0.f), 63.f);

            // l0 clamped to [0,62] so l1 = l0+1 always; weights absorb the
            // boundary cases exactly (d1 on l0 corner, d0 on l1 corner).
            int l0z = max(0, min(__float2int_rd(locz), 62));
            int l0y = max(0, min(__float2int_rd(locy), 62));
            int l0x = max(0, min(__float2int_rd(locx), 62));

            float d1z = (float)(l0z + 1) - clz, d0z = 1.f - d1z;
            float d1y = (float)(l0y + 1) - cly, d0y = 1.f - d1y;
            float d1x = (float)(l0x + 1) - clx, d0x = 1.f - d1x;

            // Window slot of l0 plane (always valid, incl. edges).
            int s0z = l0z - z + 1;   // 0 or 1
            int s0y = l0y - y + 1;   // 0 or 1

            int base = (s0z * 3 + s0y) * SLAB_F2 + ibase + l0x;
            ull v000 = S2[base],                  v001 = S2[base + 1];
            ull v010 = S2[base + SLAB_F2],        v011 = S2[base + SLAB_F2 + 1];
            ull v100 = S2[base + 3 * SLAB_F2],    v101 = S2[base + 3 * SLAB_F2 + 1];
            ull v110 = S2[base + 4 * SLAB_F2],    v111 = S2[base + 4 * SLAB_F2 + 1];

            ull d1xp = pack2(d1x, d1x), d0xp = pack2(d0x, d0x);
            ull d1yp = pack2(d1y, d1y), d0yp = pack2(d0y, d0y);
            ull d1zp = pack2(d1z, d1z), d0zp = pack2(d0z, d0z);

            ull x00 = fma2(d1xp, v000, mul2(d0xp, v001));
            ull x01 = fma2(d1xp, v010, mul2(d0xp, v011));
            ull x10 = fma2(d1xp, v100, mul2(d0xp, v101));
            ull x11 = fma2(d1xp, v110, mul2(d0xp, v111));
            ull y0  = fma2(d1yp, x00, mul2(d0yp, x01));
            ull y1  = fma2(d1yp, x10, mul2(d0yp, x11));
            ull s   = fma2(d1zp, y0,  mul2(d0zp, y1));

            float m = mj[j];
            ull part = mul2(pack2(m, m), s);

            // Butterfly-sum over the 8 i-lanes of this w (lane bits 0..2 == i).
            part = add2(part, __shfl_xor_sync(0xFFFFFFFFu, part, 1));
            part = add2(part, __shfl_xor_sync(0xFFFFFFFFu, part, 2));
            part = add2(part, __shfl_xor_sync(0xFFFFFFFFu, part, 4));
            if (i == j) res = part;
        }
    }

    float a0, a1;
    unpack2(res, a0, a1);
    float bv = 8.f * bias[vox * 8 + i];

    out[vox * 8 + i]           = a0 + bv;   // batch 0 (this lane's j == i)
    out[2097152 + vox * 8 + i] = a1 + bv;   // batch 1
}

extern "C" void kernel_launch(void* const* d_in, const int* in_sizes, int n_in,
                              void* d_out, int out_size)
{
    // Identify inputs robustly by element count (all four are distinct).
    const float* x    = nullptr;  // 2*64^3*8      = 4,194,304
    const float* mult = nullptr;  // 64^3*8*8      = 16,777,216
    const float* trf  = nullptr;  // 64^3*8*8*3    = 50,331,648
    const float* bias = nullptr;  // 64^3*8        = 2,097,152
    for (int i = 0; i < n_in; i++) {
        switch (in_sizes[i]) {
            case  4194304: x    = (const float*)d_in[i]; break;
            case 16777216: mult = (const float*)d_in[i]; break;
            case 50331648: trf  = (const float*)d_in[i]; break;
            case  2097152: bias = (const float*)d_in[i]; break;
            default: break;
        }
    }
    if (!x)    x    = (const float*)d_in[0];
    if (!mult) mult = (const float*)d_in[1];
    if (!trf)  trf  = (const float*)d_in[2];
    if (!bias) bias = (const float*)d_in[3];

    dim3 grid(64, 64, 1);
    lclt_kernel<<<grid, 512>>>(x, mult, trf, bias, (float*)d_out);
}